// round 17
// baseline (speedup 1.0000x reference)
#include <cuda_runtime.h>
#include <cuda_fp16.h>
#include <cstdint>

// ---------------- problem constants ----------------
#define BATCH   8
#define NT      8192
#define NS      2048
#define NTOT    (BATCH * NT)      // 65536 target rows
#define C_TGT   128
#define C_SRC   256
#define C_IN    384
#define C_HID   256
#define C_OUT   128

// ---------------- device scratch (no allocs allowed) ----------------
__device__ __align__(128) __half g_interp_h[NTOT * C_SRC];   // 32 MB
__device__ __align__(128) __half g_hidden_h[NTOT * C_HID];   // 32 MB
__device__ __align__(128) __half g_xt_h   [NTOT * C_TGT];    // 16 MB
__device__ __align__(128) __half g_W1_h   [C_IN * C_HID];
__device__ __align__(128) __half g_Wcat_h [(C_HID + C_IN) * C_OUT];  // [W2;Ws]
__device__ __align__(128) float  g_bcat   [C_OUT];                   // b2+bs

// ============================================================
// low-level helpers
// ============================================================
__device__ __forceinline__ uint32_t smem_u32(const void* p) {
    return (uint32_t)__cvta_generic_to_shared(p);
}
__device__ __forceinline__ void cp16h(__half* dst_smem, const __half* src_gmem) {
    uint32_t d = smem_u32(dst_smem);
    asm volatile("cp.async.cg.shared.global [%0], [%1], 16;\n" :: "r"(d), "l"(src_gmem));
}
__device__ __forceinline__ void cp_commit() { asm volatile("cp.async.commit_group;\n"); }
template<int N>
__device__ __forceinline__ void cp_wait()   { asm volatile("cp.async.wait_group %0;\n" :: "n"(N)); }

__device__ __forceinline__ void ldsm_x4(uint32_t r[4], uint32_t addr) {
    asm volatile("ldmatrix.sync.aligned.m8n8.x4.shared.b16 {%0,%1,%2,%3}, [%4];"
        : "=r"(r[0]), "=r"(r[1]), "=r"(r[2]), "=r"(r[3]) : "r"(addr));
}
__device__ __forceinline__ void ldsm_x4t(uint32_t r[4], uint32_t addr) {
    asm volatile("ldmatrix.sync.aligned.m8n8.x4.trans.shared.b16 {%0,%1,%2,%3}, [%4];"
        : "=r"(r[0]), "=r"(r[1]), "=r"(r[2]), "=r"(r[3]) : "r"(addr));
}
__device__ __forceinline__ void mma16816(float d[4], const uint32_t a[4],
                                         uint32_t b0, uint32_t b1) {
    asm volatile(
        "mma.sync.aligned.m16n8k16.row.col.f32.f16.f16.f32 "
        "{%0,%1,%2,%3}, {%4,%5,%6,%7}, {%8,%9}, {%0,%1,%2,%3};"
        : "+f"(d[0]), "+f"(d[1]), "+f"(d[2]), "+f"(d[3])
        : "r"(a[0]), "r"(a[1]), "r"(a[2]), "r"(a[3]), "r"(b0), "r"(b1));
}

// per-warp compute of one KC=64 chunk (4 k16 steps), 1-step register
// double buffer. A pitch fixed at 72 halves; SBLD = B pitch in halves.
template<int SBLD>
__device__ __forceinline__ void compute_chunk64(
    uint32_t aBase, uint32_t bBase, float fc[2][8][4])
{
    uint32_t a[2][2][4];
    uint32_t b[2][4][4];

    #pragma unroll
    for (int mi = 0; mi < 2; ++mi)
        ldsm_x4(a[0][mi], aBase + mi * (16 * 72 * 2));
    #pragma unroll
    for (int nt = 0; nt < 4; ++nt)
        ldsm_x4t(b[0][nt], bBase + nt * 32);

    #pragma unroll
    for (int s = 0; s < 4; ++s) {
        const int cur = s & 1, nxt = cur ^ 1;
        if (s < 3) {
            #pragma unroll
            for (int mi = 0; mi < 2; ++mi)
                ldsm_x4(a[nxt][mi], aBase + mi * (16 * 72 * 2) + (s + 1) * 32);
            #pragma unroll
            for (int nt = 0; nt < 4; ++nt)
                ldsm_x4t(b[nxt][nt], bBase + nt * 32 + (s + 1) * (16 * SBLD * 2));
        }
        #pragma unroll
        for (int mi = 0; mi < 2; ++mi)
            #pragma unroll
            for (int nt = 0; nt < 4; ++nt) {
                mma16816(fc[mi][nt*2+0], a[cur][mi], b[cur][nt][0], b[cur][nt][1]);
                mma16816(fc[mi][nt*2+1], a[cur][mi], b[cur][nt][2], b[cur][nt][3]);
            }
    }
}

// ============================================================
// Kernel 1: fused  weight-cvt + xt-cvt + 3-NN (split-4) + interp gather.
// 512 blocks x 512 threads; one block owns 128 target rows.
// ============================================================
__global__ __launch_bounds__(512)
void knn_interp_kernel(const float* __restrict__ pos_t, const float* __restrict__ pos_s,
                       const float* __restrict__ xs,   const float* __restrict__ xt,
                       const float* __restrict__ W1,   const float* __restrict__ W2,
                       const float* __restrict__ Ws,   const float* __restrict__ b2,
                       const float* __restrict__ bs)
{
    const int tid = threadIdx.x;
    const int gi  = blockIdx.x * 512 + tid;

    // --- fused weight cvt (first blocks only; bounds-checked) ---
    if (gi < C_IN * C_HID)   g_W1_h[gi] = __float2half_rn(W1[gi]);
    if (gi < C_HID * C_OUT)  g_Wcat_h[gi] = __float2half_rn(W2[gi]);
    if (gi < C_IN * C_OUT)   g_Wcat_h[C_HID * C_OUT + gi] = __float2half_rn(Ws[gi]);
    if (gi < C_OUT)          g_bcat[gi] = b2[gi] + bs[gi];

    // --- fused xt cvt: exactly 8 float4 per thread (2,097,152 total) ---
    #pragma unroll
    for (int k = 0; k < 8; ++k) {
        const int i4 = gi + k * (512 * 512);
        float4 v = ((const float4*)xt)[i4];
        __half2* p = (__half2*)&g_xt_h[i4 * 4];
        p[0] = __floats2half2_rn(v.x, v.y);
        p[1] = __floats2half2_rn(v.z, v.w);
    }

    __shared__ float4 sp[NS];          // 32 KB source positions
    __shared__ int    sidx[128 * 3];
    __shared__ float  sww [128 * 3];

    const int b    = blockIdx.x >> 6;
    const int tile = blockIdx.x & 63;

    const float* ps = pos_s + (size_t)b * NS * 3;
    for (int s = tid; s < NS; s += 512)
        sp[s] = make_float4(ps[3*s], ps[3*s+1], ps[3*s+2], 0.f);
    __syncthreads();

    // --- split-4 knn: 4 consecutive lanes per target ---
    const int tl = tid >> 2;           // 0..127 local target
    const int q  = tid & 3;
    const int t  = (b * 64 + tile) * 128 + tl;
    const float tx = pos_t[3*t], ty = pos_t[3*t+1], tz = pos_t[3*t+2];

    const int sbeg = q * (NS / 4);
    float d0 = 1e30f, d1 = 1e30f, d2 = 1e30f;
    int   i0 = sbeg,  i1 = sbeg,  i2 = sbeg;

    #pragma unroll 4
    for (int s = sbeg; s < sbeg + NS/4; ++s) {
        float4 p = sp[s];
        float dx = tx - p.x, dy = ty - p.y, dz = tz - p.z;
        float d  = fmaf(dz, dz, fmaf(dy, dy, dx * dx));
        if (d < d2) {
            if (d < d1) {
                d2 = d1; i2 = i1;
                if (d < d0) { d1 = d0; i1 = i0; d0 = d; i0 = s; }
                else        { d1 = d;  i1 = s; }
            } else { d2 = d; i2 = s; }
        }
    }

    auto ins = [&](float d, int s) {
        if (d < d2) {
            if (d < d1) {
                d2 = d1; i2 = i1;
                if (d < d0) { d1 = d0; i1 = i0; d0 = d; i0 = s; }
                else        { d1 = d;  i1 = s; }
            } else { d2 = d; i2 = s; }
        }
    };
    const unsigned msk = 0xffffffffu;
    #pragma unroll
    for (int delta = 1; delta <= 2; delta <<= 1) {
        float e0 = __shfl_xor_sync(msk, d0, delta);
        float e1 = __shfl_xor_sync(msk, d1, delta);
        float e2 = __shfl_xor_sync(msk, d2, delta);
        int   j0 = __shfl_xor_sync(msk, i0, delta);
        int   j1 = __shfl_xor_sync(msk, i1, delta);
        int   j2 = __shfl_xor_sync(msk, i2, delta);
        ins(e0, j0); ins(e1, j1); ins(e2, j2);
    }

    if (q == 0) {   // lane with index-order-preserving insertion history
        const float w0 = 1.f / fmaxf(d0, 1e-16f);
        const float w1 = 1.f / fmaxf(d1, 1e-16f);
        const float w2 = 1.f / fmaxf(d2, 1e-16f);
        const float inv = 1.f / (w0 + w1 + w2);
        sidx[tl*3+0] = b * NS + i0;
        sidx[tl*3+1] = b * NS + i1;
        sidx[tl*3+2] = b * NS + i2;
        sww [tl*3+0] = w0 * inv;
        sww [tl*3+1] = w1 * inv;
        sww [tl*3+2] = w2 * inv;
    }
    __syncthreads();

    // --- interp gather: 16 warps x 8 rows, half output ---
    const int w    = tid >> 5;
    const int lane = tid & 31;
    #pragma unroll 1
    for (int iter = 0; iter < 8; ++iter) {
        const int rr = iter * 16 + w;                 // 0..127
        const int row = (b * 64 + tile) * 128 + rr;
        const int   k0 = sidx[rr*3+0];
        const int   k1 = sidx[rr*3+1];
        const int   k2 = sidx[rr*3+2];
        const float w0 = sww[rr*3+0];
        const float w1 = sww[rr*3+1];
        const float w2 = sww[rr*3+2];
        const float4* s0 = (const float4*)(xs + (size_t)k0 * C_SRC);
        const float4* s1 = (const float4*)(xs + (size_t)k1 * C_SRC);
        const float4* s2 = (const float4*)(xs + (size_t)k2 * C_SRC);
        __half2* dst = (__half2*)&g_interp_h[(size_t)row * C_SRC];
        #pragma unroll
        for (int h = 0; h < 2; ++h) {
            const int c = lane + h * 32;              // float4 idx, 64/row
            float4 a = s0[c], bb = s1[c], d = s2[c];
            float rx = w0*a.x + w1*bb.x + w2*d.x;
            float ry = w0*a.y + w1*bb.y + w2*d.y;
            float rz = w0*a.z + w1*bb.z + w2*d.z;
            float rw = w0*a.w + w1*bb.w + w2*d.w;
            dst[c*2+0] = __floats2half2_rn(rx, ry);
            dst[c*2+1] = __floats2half2_rn(rz, rw);
        }
    }
}

// ============================================================
// GEMM1: 64x256 block tile (full N), 256 threads (8 warps, 2x4),
// warp tile 32x64, KC=64, 2-stage cp.async, 2 CTAs/SM.
// ============================================================
#define SA1_LD   72
#define SA1_HSZ  (64 * SA1_LD)            // 4608 halves
#define SB1_LD   264                      // 256 + 8 pad
#define SB1_HSZ  (64 * SB1_LD)            // 16896 halves
#define STG1_H   (SA1_HSZ + SB1_HSZ)      // 21504 halves
#define STG1_B   (STG1_H * 2)             // 43008 bytes
#define G1_SMEM  (2 * STG1_B)             // 86016 bytes

__global__ __launch_bounds__(256, 2)
void gemm1_kernel(const float* __restrict__ b1)
{
    extern __shared__ __align__(16) __half sh[];
    const int m0 = blockIdx.x * 64;
    const int tid = threadIdx.x;
    const int w   = tid >> 5;
    const int wm  = w & 1;       // 2 x 32-row groups (M=64)
    const int wn  = w >> 1;      // 4 x 64-col groups (N=256)
    const int lane = tid & 31;

    const uint32_t sb = smem_u32(sh);
    const uint32_t aLaneOff = ((wm*32 + (lane & 15)) * SA1_LD + (lane >> 4) * 8) * 2;
    const uint32_t bLaneOff = ((lane & 15) * SB1_LD + wn*64 + (lane >> 4) * 8) * 2;

    float fc[2][8][4];
    #pragma unroll
    for (int i = 0; i < 2; ++i)
        #pragma unroll
        for (int j = 0; j < 8; ++j)
            #pragma unroll
            for (int qq = 0; qq < 4; ++qq) fc[i][j][qq] = 0.f;

    auto stage_it = [&](int it) {
        const int kc = it * 64;
        const __half* ab; int as, ao;
        if (kc < C_TGT) { ab = g_xt_h;     as = C_TGT; ao = kc;         }
        else            { ab = g_interp_h; as = C_SRC; ao = kc - C_TGT; }
        __half* sA = sh + (it & 1) * STG1_H;
        __half* sB = sA + SA1_HSZ;
        #pragma unroll
        for (int t = 0; t < 2; ++t) {                 // A: 512 x 16B
            const int i = tid + t * 256;
            const int r  = i >> 3;                    // 0..63
            const int c8 = (i & 7) << 3;
            cp16h(&sA[r * SA1_LD + c8], ab + (size_t)(m0 + r) * as + ao + c8);
        }
        #pragma unroll
        for (int t = 0; t < 8; ++t) {                 // B: 2048 x 16B
            const int i = tid + t * 256;
            const int r  = i >> 5;                    // 0..63
            const int c8 = (i & 31) << 3;
            cp16h(&sB[r * SB1_LD + c8], g_W1_h + (size_t)(kc + r) * C_HID + c8);
        }
        cp_commit();
    };

    const int NITER = C_IN / 64;   // 6
    stage_it(0);
    stage_it(1);

    for (int it = 0; it < NITER; ++it) {
        if (it < NITER - 1) cp_wait<1>(); else cp_wait<0>();
        __syncthreads();
        const uint32_t stg = sb + (it & 1) * STG1_B;
        compute_chunk64<SB1_LD>(stg + aLaneOff, stg + SA1_HSZ * 2 + bLaneOff, fc);
        if (it + 2 < NITER) {
            __syncthreads();
            stage_it(it + 2);
        }
    }

    // epilogue: bias + relu -> half hidden (direct stores)
    const int r0 = m0 + wm*32 + (lane >> 2);
    #pragma unroll
    for (int mi = 0; mi < 2; ++mi) {
        const int ra = r0 + mi*16, rb = ra + 8;
        #pragma unroll
        for (int nj = 0; nj < 8; ++nj) {
            const int col = wn*64 + nj*8 + (lane & 3)*2;
            float2 bb = *(const float2*)&b1[col];
            float* d = fc[mi][nj];
            __half2 h0 = __floats2half2_rn(fmaxf(d[0]+bb.x, 0.f), fmaxf(d[1]+bb.y, 0.f));
            __half2 h1 = __floats2half2_rn(fmaxf(d[2]+bb.x, 0.f), fmaxf(d[3]+bb.y, 0.f));
            *(__half2*)&g_hidden_h[(size_t)ra * C_HID + col] = h0;
            *(__half2*)&g_hidden_h[(size_t)rb * C_HID + col] = h1;
        }
    }
}

// ============================================================
// GEMM2: 128x128 tile, 8 warps (4x2), KC=64, 3-stage (proven).
// ============================================================
#define SA2_LD   72
#define SA2_HSZ  (128 * SA2_LD)           // 9216 halves
#define SB2_LD   136
#define SB2_HSZ  (64 * SB2_LD)            // 8704 halves
#define STG2_H   (SA2_HSZ + SB2_HSZ)      // 17920 halves
#define STG2_B   (STG2_H * 2)             // 35840 bytes
#define G2_SMEM  (3 * STG2_B)             // 107520 bytes

__global__ __launch_bounds__(256, 2)
void gemm2_kernel(float* __restrict__ out)
{
    extern __shared__ __align__(16) __half sh[];
    const int m0 = blockIdx.x * 128;
    const int tid = threadIdx.x;
    const int w   = tid >> 5;
    const int wm  = w & 3;
    const int wn  = w >> 2;
    const int lane = tid & 31;

    const uint32_t sb = smem_u32(sh);
    const uint32_t aLaneOff = ((wm*32 + (lane & 15)) * SA2_LD + (lane >> 4) * 8) * 2;
    const uint32_t bLaneOff = ((lane & 15) * SB2_LD + wn*64 + (lane >> 4) * 8) * 2;

    float fc[2][8][4];
    #pragma unroll
    for (int i = 0; i < 2; ++i)
        #pragma unroll
        for (int j = 0; j < 8; ++j)
            #pragma unroll
            for (int qq = 0; qq < 4; ++qq) fc[i][j][qq] = 0.f;

    auto stage_it = [&](int it) {
        const int kc = it * 64;
        const __half* ab; int as, ao;
        if      (kc < 256) { ab = g_hidden_h; as = C_HID; ao = kc;       }
        else if (kc < 384) { ab = g_xt_h;     as = C_TGT; ao = kc - 256; }
        else               { ab = g_interp_h; as = C_SRC; ao = kc - 384; }
        __half* sA = sh + (it % 3) * STG2_H;
        __half* sB = sA + SA2_HSZ;
        #pragma unroll
        for (int t = 0; t < 4; ++t) {                 // A: 1024 x 16B
            const int i = tid + t * 256;
            const int r  = i >> 3;
            const int c8 = (i & 7) << 3;
            cp16h(&sA[r * SA2_LD + c8], ab + (size_t)(m0 + r) * as + ao + c8);
        }
        #pragma unroll
        for (int t = 0; t < 4; ++t) {                 // B: 1024 x 16B
            const int i = tid + t * 256;
            const int r  = i >> 4;
            const int c8 = (i & 15) << 3;
            cp16h(&sB[r * SB2_LD + c8], g_Wcat_h + (size_t)(kc + r) * C_OUT + c8);
        }
        cp_commit();
    };

    const int NITER = (C_HID + C_IN) / 64;   // 10
    stage_it(0);
    stage_it(1);

    for (int it = 0; it < NITER; ++it) {
        cp_wait<1>();
        __syncthreads();
        if (it + 2 < NITER) stage_it(it + 2);
        else cp_commit();
        const uint32_t stg = sb + (it % 3) * STG2_B;
        compute_chunk64<SB2_LD>(stg + aLaneOff, stg + SA2_HSZ * 2 + bLaneOff, fc);
    }

    // epilogue: bcat + relu -> fp32 out
    const int r0 = m0 + wm*32 + (lane >> 2);
    #pragma unroll
    for (int mi = 0; mi < 2; ++mi) {
        const int ra = r0 + mi*16, rb = ra + 8;
        #pragma unroll
        for (int nj = 0; nj < 8; ++nj) {
            const int col = wn*64 + nj*8 + (lane & 3)*2;
            float2 bb = *(const float2*)&g_bcat[col];
            float* d = fc[mi][nj];
            float2 v0 = make_float2(fmaxf(d[0]+bb.x, 0.f), fmaxf(d[1]+bb.y, 0.f));
            float2 v1 = make_float2(fmaxf(d[2]+bb.x, 0.f), fmaxf(d[3]+bb.y, 0.f));
            *(float2*)&out[(size_t)ra * C_OUT + col] = v0;
            *(float2*)&out[(size_t)rb * C_OUT + col] = v1;
        }
    }
}

// ============================================================
// Launch.
// ============================================================
extern "C" void kernel_launch(void* const* d_in, const int* in_sizes, int n_in,
                              void* d_out, int out_size)
{
    const float* xt = (const float*)d_in[0];
    const float* pt = (const float*)d_in[1];
    const float* xs = (const float*)d_in[3];
    const float* ps = (const float*)d_in[4];
    const float* W1 = (const float*)d_in[6];
    const float* b1 = (const float*)d_in[7];
    const float* W2 = (const float*)d_in[8];
    const float* b2 = (const float*)d_in[9];
    const float* Ws = (const float*)d_in[10];
    const float* bs = (const float*)d_in[11];
    float* out = (float*)d_out;

    cudaFuncSetAttribute(gemm1_kernel, cudaFuncAttributeMaxDynamicSharedMemorySize, G1_SMEM);
    cudaFuncSetAttribute(gemm2_kernel, cudaFuncAttributeMaxDynamicSharedMemorySize, G2_SMEM);

    knn_interp_kernel<<<512, 512>>>(pt, ps, xs, xt, W1, W2, Ws, b2, bs);
    gemm1_kernel     <<<NTOT / 64, 256, G1_SMEM>>>(b1);
    gemm2_kernel     <<<NTOT / 128, 256, G2_SMEM>>>(out);
}